// round 9
// baseline (speedup 1.0000x reference)
#include <cuda_runtime.h>
#include <cstdint>
#include <cstddef>

#define Dv 100
typedef unsigned long long ull;

__device__ __forceinline__ void ffma2(ull &d, ull a, ull b) {
    asm("fma.rn.f32x2 %0, %1, %2, %0;" : "+l"(d) : "l"(a), "l"(b));
}
__device__ __forceinline__ ull dup2(float v) {
    ull r; asm("mov.b64 %0, {%1, %1};" : "=l"(r) : "f"(v)); return r;
}
__device__ __forceinline__ ull pack2(float lo, float hi) {
    ull r; asm("mov.b64 %0, {%1, %2};" : "=l"(r) : "f"(lo), "f"(hi)); return r;
}
__device__ __forceinline__ float2 unpack2(ull v) {
    float2 r; asm("mov.b64 {%0, %1}, %2;" : "=f"(r.x), "=f"(r.y) : "l"(v)); return r;
}
__device__ __forceinline__ void lds16(ull &a, ull &b, const void* p) {
    unsigned sa = (unsigned)__cvta_generic_to_shared(p);
    asm("ld.shared.v2.u64 {%0, %1}, [%2];" : "=l"(a), "=l"(b) : "r"(sa));
}
// (mz >= 0) ? 0 : xv  — with mz = nla - n = -(la+noise): gives (la+noise>0) ? xv : 0
__device__ __forceinline__ float slct0(float xv, float mz) {
    float r;
    asm("slct.f32.f32 %0, %1, %2, %3;" : "=f"(r) : "f"(0.0f), "f"(xv), "f"(mz));
    return r;
}
__device__ __forceinline__ void cp16(unsigned dst, const void* src) {
    asm volatile("cp.async.cg.shared.global [%0], [%1], 16;" :: "r"(dst), "l"(src) : "memory");
}
__device__ __forceinline__ float lrelu(float a) { return fmaxf(a, 0.01f * a); }

struct Smem {
    float w0s[Dv][2][8][8];   // [j][ih][tt][i-in-half] = W0[t0+tt][ih*8+k][j]   51200B
    float nlas[Dv][8];        // -log_alpha[j][t]; +3e38 if j==t or t>=100        3200B
    float w1s[16][16][8];     // [jj][2tt+ih][k] = W1[t0+tt][ih*8+k][jj]          8192B
    float ring[4][4][704];    // [warp][stage]: noise 4x640B (bs-offset 320) + x 256B  45056B
};                            // total 107648B -> 2 blocks/SM

#define NOISE_LIMIT 40959996L   // last valid 16B-aligned element start in noise

__global__ __launch_bounds__(128, 2)
void fused_nri_kernel(const float* __restrict__ x,
                      const float* __restrict__ la_g,
                      const float* __restrict__ noise,
                      const float* __restrict__ W0,
                      const float* __restrict__ b0g,
                      const float* __restrict__ W1,
                      const float* __restrict__ b1g,
                      const float* __restrict__ W2,
                      const float* __restrict__ b2g,
                      float* __restrict__ out)
{
    extern __shared__ char smem_raw[];
    Smem& S = *reinterpret_cast<Smem*>(smem_raw);
    const int tid  = threadIdx.x;
    const int lane = tid & 31;
    const int warp = tid >> 5;
    const int t_tile = blockIdx.x >> 6;
    const int b_blk  = blockIdx.x & 63;
    const int t0 = t_tile * 8;
    const int bbase = b_blk * 64;
    const int rowg0 = bbase + warp * 16;    // this warp's 16 batch rows

    // ---- per-lane cp.async plan: 4 noise quads + (lane<16) 1 x quad per chunk ----
    long nsrc[4]; unsigned ndst[4];
    #pragma unroll
    for (int u = 0; u < 4; u++) {
        int q = lane + u * 32;                 // 0..127
        int h = q & 1, row = (q >> 1) & 15, jj = q >> 5;
        nsrc[u] = (long)(rowg0 + row) * 10000 + (long)(jj * 100 + t0 + h * 4);
        ndst[u] = (unsigned)(jj * 640 + (row >> 3) * 320 + (row & 7) * 32 + h * 16);
    }
    const bool do_x = lane < 16;
    const long xsrc0 = (long)(rowg0 + (lane & 15)) * 100;
    const unsigned xdst = (unsigned)(2560 + ((lane >> 3) & 1) * 128 + (lane & 7) * 16);
    const unsigned rb = (unsigned)__cvta_generic_to_shared(&S.ring[warp][0][0]);

    #define ISSUE(c) do {                                                     \
        unsigned _sb = rb + (unsigned)(((c) & 3) * 2816);                     \
        long _off = (long)(c) * 400;                                          \
        _Pragma("unroll")                                                     \
        for (int _u = 0; _u < 4; _u++) {                                      \
            long _s = nsrc[_u] + _off;                                        \
            if (_s > NOISE_LIMIT) _s = NOISE_LIMIT;                           \
            cp16(_sb + ndst[_u], noise + _s);                                 \
        }                                                                     \
        if (do_x) cp16(_sb + xdst, x + xsrc0 + (long)(c) * 4);                \
    } while (0)

    // prologue: 3 chunks in flight before anything else
    ISSUE(0); asm volatile("cp.async.commit_group;" ::: "memory");
    ISSUE(1); asm volatile("cp.async.commit_group;" ::: "memory");
    ISSUE(2); asm volatile("cp.async.commit_group;" ::: "memory");

    // ---- stage W0 (coalesced over j) ----
    for (int e = tid; e < 8 * 16 * Dv; e += 128) {
        int tw = e / (16 * Dv);
        int r  = e - tw * 16 * Dv;
        int i  = r / Dv;
        int j  = r - i * Dv;
        int tg = t0 + tw;
        float v = (tg < Dv) ? W0[(tg * 16 + i) * Dv + j] : 0.f;
        S.w0s[j][i >> 3][tw][i & 7] = v;
    }
    // ---- negated log_alpha with adj + tile guard folded in ----
    for (int e = tid; e < 8 * Dv; e += 128) {
        int j = e >> 3, tw = e & 7, tg = t0 + tw;
        float v = 3e38f;
        if (tg < Dv && j != tg) v = -la_g[j * Dv + tg];
        S.nlas[j][tw] = v;
    }
    // ---- W1 as [jj][2tt+ih][k] ----
    for (int e = tid; e < 8 * 16 * 16; e += 128) {
        int tw = e >> 8, r = e & 255, i = r >> 4, jj = r & 15, tg = t0 + tw;
        S.w1s[jj][tw * 2 + (i >> 3)][i & 7] = (tg < Dv) ? W1[(tg * 16 + i) * 16 + jj] : 0.f;
    }
    __syncthreads();

    const int tt = lane & 7;          // t within tile
    const int ih = (lane >> 3) & 1;   // i half
    const int bs = lane >> 4;         // row half (8 rows each)
    const int t  = t0 + tt;

    ull acc[8][4];
    #pragma unroll
    for (int r = 0; r < 8; r++)
        #pragma unroll
        for (int q = 0; q < 4; q++) acc[r][q] = 0ull;

    // ---- main loop: 25 chunks of 4 j, warp-private 4-stage pipeline ----
    for (int c = 0; c < 25; c++) {
        asm volatile("cp.async.wait_group 2;" ::: "memory");
        __syncwarp();
        if (c + 3 < 25) ISSUE(c + 3);        // target stage (c+3)&3 freed in iter c-1
        asm volatile("cp.async.commit_group;" ::: "memory");

        const float* sp = &S.ring[warp][c & 3][0];
        float4 xr[8];
        #pragma unroll
        for (int r = 0; r < 8; r++)
            xr[r] = *reinterpret_cast<const float4*>(sp + 640 + bs * 32 + r * 4);

        #pragma unroll
        for (int jj = 0; jj < 4; jj++) {
            const int j = 4 * c + jj;
            ull w0a, w0b, w0c, w0d;
            lds16(w0a, w0b, &S.w0s[j][ih][tt][0]);
            lds16(w0c, w0d, &S.w0s[j][ih][tt][4]);
            const float nla = S.nlas[j][tt];
            const float* np = sp + jj * 160 + bs * 80 + tt;
            #pragma unroll
            for (int r = 0; r < 8; r++) {
                float n = np[r * 8];
                float xv = (jj == 0) ? xr[r].x : (jj == 1) ? xr[r].y
                         : (jj == 2) ? xr[r].z : xr[r].w;
                ull xp = dup2(slct0(xv, nla - n));
                ffma2(acc[r][0], w0a, xp);
                ffma2(acc[r][1], w0b, xp);
                ffma2(acc[r][2], w0c, xp);
                ffma2(acc[r][3], w0d, xp);
            }
        }
    }
    #undef ISSUE
    asm volatile("cp.async.wait_group 0;" ::: "memory");

    // ---- epilogue: layers 1 & 2, i-halves combined via shfl_xor(8) ----
    const int t_eff = (t < Dv) ? t : (Dv - 1);
    ull b0p[4], b1p[4], w2p0[4], w2p1[4];
    {
        const float4* p0 = reinterpret_cast<const float4*>(b0g + t_eff * 16 + ih * 8);
        const float4* p1 = reinterpret_cast<const float4*>(b1g + t_eff * 16 + ih * 8);
        const float4* p2 = reinterpret_cast<const float4*>(W2 + t_eff * 32 + ih * 8);
        const float4* p3 = reinterpret_cast<const float4*>(W2 + t_eff * 32 + 16 + ih * 8);
        float4 a0 = p0[0], a1 = p0[1], c0 = p1[0], c1 = p1[1];
        float4 d0 = p2[0], d1 = p2[1], e0 = p3[0], e1 = p3[1];
        b0p[0] = pack2(a0.x, a0.y); b0p[1] = pack2(a0.z, a0.w);
        b0p[2] = pack2(a1.x, a1.y); b0p[3] = pack2(a1.z, a1.w);
        b1p[0] = pack2(c0.x, c0.y); b1p[1] = pack2(c0.z, c0.w);
        b1p[2] = pack2(c1.x, c1.y); b1p[3] = pack2(c1.z, c1.w);
        w2p0[0] = pack2(d0.x, d0.y); w2p0[1] = pack2(d0.z, d0.w);
        w2p0[2] = pack2(d1.x, d1.y); w2p0[3] = pack2(d1.z, d1.w);
        w2p1[0] = pack2(e0.x, e0.y); w2p1[1] = pack2(e0.z, e0.w);
        w2p1[2] = pack2(e1.x, e1.y); w2p1[3] = pack2(e1.z, e1.w);
    }
    float2 b2v = *reinterpret_cast<const float2*>(b2g + t_eff * 2);

    #pragma unroll
    for (int pass = 0; pass < 2; pass++) {
        // h for 4 rows, my i-half (these are layer-1 inputs jj = ih*8..+7)
        ull hA[4][4], hB[4][4], a2[4][4];
        #pragma unroll
        for (int r = 0; r < 4; r++)
            #pragma unroll
            for (int q = 0; q < 4; q++) {
                float2 a = unpack2(acc[pass * 4 + r][q]);
                float2 b = unpack2(b0p[q]);
                hA[r][q] = pack2(lrelu(a.x + b.x), lrelu(a.y + b.y));
            }
        #pragma unroll
        for (int r = 0; r < 4; r++)
            #pragma unroll
            for (int q = 0; q < 4; q++) {
                hB[r][q] = __shfl_xor_sync(0xffffffffu, hA[r][q], 8);
                a2[r][q] = b1p[q];
            }
        // accumulate a2 (my i'-half) over all 16 jj: 8 from hA (jj=ih*8+m), 8 from hB
        #pragma unroll
        for (int m = 0; m < 8; m++) {
            ull wa0, wa1, wa2, wa3, wb0, wb1, wb2, wb3;
            lds16(wa0, wa1, &S.w1s[ih * 8 + m][tt * 2 + ih][0]);
            lds16(wa2, wa3, &S.w1s[ih * 8 + m][tt * 2 + ih][4]);
            lds16(wb0, wb1, &S.w1s[(1 - ih) * 8 + m][tt * 2 + ih][0]);
            lds16(wb2, wb3, &S.w1s[(1 - ih) * 8 + m][tt * 2 + ih][4]);
            #pragma unroll
            for (int r = 0; r < 4; r++) {
                float2 ha = unpack2(hA[r][m >> 1]);
                ull hv = dup2((m & 1) ? ha.y : ha.x);
                ffma2(a2[r][0], wa0, hv); ffma2(a2[r][1], wa1, hv);
                ffma2(a2[r][2], wa2, hv); ffma2(a2[r][3], wa3, hv);
                float2 hb = unpack2(hB[r][m >> 1]);
                ull hv2 = dup2((m & 1) ? hb.y : hb.x);
                ffma2(a2[r][0], wb0, hv2); ffma2(a2[r][1], wb1, hv2);
                ffma2(a2[r][2], wb2, hv2); ffma2(a2[r][3], wb3, hv2);
            }
        }
        // layer 2: partial over my i'-half, combine via shfl
        #pragma unroll
        for (int r = 0; r < 4; r++) {
            ull o0p = 0ull, o1p = 0ull;
            #pragma unroll
            for (int q = 0; q < 4; q++) {
                float2 g = unpack2(a2[r][q]);
                ull gp = pack2(lrelu(g.x), lrelu(g.y));
                ffma2(o0p, w2p0[q], gp);
                ffma2(o1p, w2p1[q], gp);
            }
            float2 s0 = unpack2(o0p), s1 = unpack2(o1p);
            float o0 = s0.x + s0.y, o1 = s1.x + s1.y;
            o0 += __shfl_xor_sync(0xffffffffu, o0, 8);
            o1 += __shfl_xor_sync(0xffffffffu, o1, 8);
            if (ih == 0 && t < Dv) {
                int b = bbase + warp * 16 + bs * 8 + pass * 4 + r;
                reinterpret_cast<float2*>(out)[b * Dv + t] =
                    make_float2(o0 + b2v.x, o1 + b2v.y);
            }
        }
    }
}

extern "C" void kernel_launch(void* const* d_in, const int* in_sizes, int n_in,
                              void* d_out, int out_size)
{
    const float* x   = (const float*)d_in[0];
    const float* la  = (const float*)d_in[1];
    const float* nz  = (const float*)d_in[2];
    const float* W0  = (const float*)d_in[3];
    const float* b0  = (const float*)d_in[4];
    const float* W1  = (const float*)d_in[5];
    const float* b1  = (const float*)d_in[6];
    const float* W2  = (const float*)d_in[7];
    const float* b2  = (const float*)d_in[8];
    float* out = (float*)d_out;

    cudaFuncSetAttribute(fused_nri_kernel,
                         cudaFuncAttributeMaxDynamicSharedMemorySize,
                         (int)sizeof(Smem));
    // 13 t-tiles x 64 b-blocks, 128 threads (4 warps x 16 rows)
    fused_nri_kernel<<<13 * 64, 128, sizeof(Smem)>>>(
        x, la, nz, W0, b0, W1, b1, W2, b2, out);
}

// round 10
// speedup vs baseline: 1.0136x; 1.0136x over previous
#include <cuda_runtime.h>
#include <cstdint>
#include <cstddef>

#define Dv 100
typedef unsigned long long ull;

__device__ __forceinline__ void ffma2(ull &d, ull a, ull b) {
    asm("fma.rn.f32x2 %0, %1, %2, %0;" : "+l"(d) : "l"(a), "l"(b));
}
__device__ __forceinline__ ull dup2(float v) {
    ull r; asm("mov.b64 %0, {%1, %1};" : "=l"(r) : "f"(v)); return r;
}
__device__ __forceinline__ ull pack2(float lo, float hi) {
    ull r; asm("mov.b64 %0, {%1, %2};" : "=l"(r) : "f"(lo), "f"(hi)); return r;
}
__device__ __forceinline__ float2 unpack2(ull v) {
    float2 r; asm("mov.b64 {%0, %1}, %2;" : "=f"(r.x), "=f"(r.y) : "l"(v)); return r;
}
__device__ __forceinline__ void lds16(ull &a, ull &b, const void* p) {
    unsigned sa = (unsigned)__cvta_generic_to_shared(p);
    asm("ld.shared.v2.u64 {%0, %1}, [%2];" : "=l"(a), "=l"(b) : "r"(sa));
}
// (mz >= 0) ? 0 : xv  — with mz = nla - n = -(la+noise): gives (la+noise>0) ? xv : 0
__device__ __forceinline__ float slct0(float xv, float mz) {
    float r;
    asm("slct.f32.f32 %0, %1, %2, %3;" : "=f"(r) : "f"(0.0f), "f"(xv), "f"(mz));
    return r;
}
__device__ __forceinline__ void cp16(unsigned dst, const void* src) {
    asm volatile("cp.async.cg.shared.global [%0], [%1], 16;" :: "r"(dst), "l"(src) : "memory");
}
__device__ __forceinline__ float lrelu(float a) { return fmaxf(a, 0.01f * a); }

struct Smem {
    float w0s[Dv][2][8][8];   // [j][ih][tt][k] = W0[t0+tt][ih*8+k][j]          51200B
    float nlas[Dv][8];        // -log_alpha[j][t]; +3e38 if j==t or t>=100       3200B
    float w1s[16][16][8];     // [jj][2tt+ih][k] = W1[t0+tt][ih*8+k][jj]         8192B
    float ring[8][4][352];    // [warp][stage]: noise 1280B (bs off 160) + x 128B 45056B
};                            // total 107648B -> 2 x 256-thread blocks/SM

#define NOISE_LIMIT 40959996L   // last valid 16B-aligned element start in noise

__global__ __launch_bounds__(256, 2)
void fused_nri_kernel(const float* __restrict__ x,
                      const float* __restrict__ la_g,
                      const float* __restrict__ noise,
                      const float* __restrict__ W0,
                      const float* __restrict__ b0g,
                      const float* __restrict__ W1,
                      const float* __restrict__ b1g,
                      const float* __restrict__ W2,
                      const float* __restrict__ b2g,
                      float* __restrict__ out)
{
    extern __shared__ char smem_raw[];
    Smem& S = *reinterpret_cast<Smem*>(smem_raw);
    const int tid  = threadIdx.x;
    const int lane = tid & 31;
    const int warp = tid >> 5;     // 0..7
    const int t_tile = blockIdx.x >> 6;
    const int b_blk  = blockIdx.x & 63;
    const int t0 = t_tile * 8;
    const int bbase = b_blk * 64;
    const int rowg0 = bbase + warp * 8;     // this warp's 8 batch rows

    // ---- per-lane cp.async plan: 2 noise quads + (lane<8) 1 x quad per chunk ----
    long nsrc[2]; unsigned ndst[2];
    #pragma unroll
    for (int u = 0; u < 2; u++) {
        int q = lane + u * 32;               // 0..63
        int h = q & 1, row = (q >> 1) & 7, jj = q >> 4;
        nsrc[u] = (long)(rowg0 + row) * 10000 + (long)(jj * 100 + t0 + h * 4);
        ndst[u] = (unsigned)(jj * 320 + (row >> 2) * 160 + (row & 3) * 32 + h * 16);
    }
    const bool do_x = lane < 8;
    const long xsrc0 = (long)(rowg0 + lane) * 100;
    const unsigned xdst = (unsigned)(1280 + lane * 16);
    const unsigned rb = (unsigned)__cvta_generic_to_shared(&S.ring[warp][0][0]);

    #define ISSUE(c) do {                                                     \
        unsigned _sb = rb + (unsigned)(((c) & 3) * 1408);                     \
        long _off = (long)(c) * 400;                                          \
        _Pragma("unroll")                                                     \
        for (int _u = 0; _u < 2; _u++) {                                      \
            long _s = nsrc[_u] + _off;                                        \
            if (_s > NOISE_LIMIT) _s = NOISE_LIMIT;                           \
            cp16(_sb + ndst[_u], noise + _s);                                 \
        }                                                                     \
        if (do_x) cp16(_sb + xdst, x + xsrc0 + (long)(c) * 4);                \
    } while (0)

    // prologue: 3 chunks in flight before anything else
    ISSUE(0); asm volatile("cp.async.commit_group;" ::: "memory");
    ISSUE(1); asm volatile("cp.async.commit_group;" ::: "memory");
    ISSUE(2); asm volatile("cp.async.commit_group;" ::: "memory");

    // ---- stage W0 (coalesced over j) ----
    for (int e = tid; e < 8 * 16 * Dv; e += 256) {
        int tw = e / (16 * Dv);
        int r  = e - tw * 16 * Dv;
        int i  = r / Dv;
        int j  = r - i * Dv;
        int tg = t0 + tw;
        float v = (tg < Dv) ? W0[(tg * 16 + i) * Dv + j] : 0.f;
        S.w0s[j][i >> 3][tw][i & 7] = v;
    }
    // ---- negated log_alpha with adj + tile guard folded in ----
    for (int e = tid; e < 8 * Dv; e += 256) {
        int j = e >> 3, tw = e & 7, tg = t0 + tw;
        float v = 3e38f;
        if (tg < Dv && j != tg) v = -la_g[j * Dv + tg];
        S.nlas[j][tw] = v;
    }
    // ---- W1 as [jj][2tt+ih][k] ----
    for (int e = tid; e < 8 * 16 * 16; e += 256) {
        int tw = e >> 8, r = e & 255, i = r >> 4, jj = r & 15, tg = t0 + tw;
        S.w1s[jj][tw * 2 + (i >> 3)][i & 7] = (tg < Dv) ? W1[(tg * 16 + i) * 16 + jj] : 0.f;
    }
    __syncthreads();

    const int tt = lane & 7;          // t within tile
    const int ih = (lane >> 3) & 1;   // i half
    const int bs = lane >> 4;         // row half (4 rows each)
    const int t  = t0 + tt;

    ull acc[4][4];
    #pragma unroll
    for (int r = 0; r < 4; r++)
        #pragma unroll
        for (int q = 0; q < 4; q++) acc[r][q] = 0ull;

    // ---- main loop: 25 chunks of 4 j, warp-private 4-stage pipeline ----
    for (int c = 0; c < 25; c++) {
        asm volatile("cp.async.wait_group 2;" ::: "memory");
        __syncwarp();
        if (c + 3 < 25) ISSUE(c + 3);       // refills stage freed in iter c-1
        asm volatile("cp.async.commit_group;" ::: "memory");

        const float* sp = &S.ring[warp][c & 3][0];
        float4 xr[4];
        #pragma unroll
        for (int r = 0; r < 4; r++)
            xr[r] = *reinterpret_cast<const float4*>(sp + 320 + (bs * 4 + r) * 4);

        #pragma unroll
        for (int jj = 0; jj < 4; jj++) {
            const int j = 4 * c + jj;
            ull w0a, w0b, w0c, w0d;
            lds16(w0a, w0b, &S.w0s[j][ih][tt][0]);
            lds16(w0c, w0d, &S.w0s[j][ih][tt][4]);
            const float nla = S.nlas[j][tt];
            const float* np = sp + jj * 80 + bs * 40 + tt;
            #pragma unroll
            for (int r = 0; r < 4; r++) {
                float n = np[r * 8];
                float xv = (jj == 0) ? xr[r].x : (jj == 1) ? xr[r].y
                         : (jj == 2) ? xr[r].z : xr[r].w;
                ull xp = dup2(slct0(xv, nla - n));
                ffma2(acc[r][0], w0a, xp);
                ffma2(acc[r][1], w0b, xp);
                ffma2(acc[r][2], w0c, xp);
                ffma2(acc[r][3], w0d, xp);
            }
        }
    }
    #undef ISSUE
    asm volatile("cp.async.wait_group 0;" ::: "memory");

    // ---- epilogue: layers 1 & 2, i-halves combined via shfl_xor(8) ----
    const int t_eff = (t < Dv) ? t : (Dv - 1);
    ull b0p[4], b1p[4], w2p0[4], w2p1[4];
    {
        const float4* p0 = reinterpret_cast<const float4*>(b0g + t_eff * 16 + ih * 8);
        const float4* p1 = reinterpret_cast<const float4*>(b1g + t_eff * 16 + ih * 8);
        const float4* p2 = reinterpret_cast<const float4*>(W2 + t_eff * 32 + ih * 8);
        const float4* p3 = reinterpret_cast<const float4*>(W2 + t_eff * 32 + 16 + ih * 8);
        float4 a0 = p0[0], a1 = p0[1], c0 = p1[0], c1 = p1[1];
        float4 d0 = p2[0], d1 = p2[1], e0 = p3[0], e1 = p3[1];
        b0p[0] = pack2(a0.x, a0.y); b0p[1] = pack2(a0.z, a0.w);
        b0p[2] = pack2(a1.x, a1.y); b0p[3] = pack2(a1.z, a1.w);
        b1p[0] = pack2(c0.x, c0.y); b1p[1] = pack2(c0.z, c0.w);
        b1p[2] = pack2(c1.x, c1.y); b1p[3] = pack2(c1.z, c1.w);
        w2p0[0] = pack2(d0.x, d0.y); w2p0[1] = pack2(d0.z, d0.w);
        w2p0[2] = pack2(d1.x, d1.y); w2p0[3] = pack2(d1.z, d1.w);
        w2p1[0] = pack2(e0.x, e0.y); w2p1[1] = pack2(e0.z, e0.w);
        w2p1[2] = pack2(e1.x, e1.y); w2p1[3] = pack2(e1.z, e1.w);
    }
    float2 b2v = *reinterpret_cast<const float2*>(b2g + t_eff * 2);

    // h for 4 rows, my i-half (layer-1 inputs jj = ih*8..+7)
    ull hA[4][4], hB[4][4], a2[4][4];
    #pragma unroll
    for (int r = 0; r < 4; r++)
        #pragma unroll
        for (int q = 0; q < 4; q++) {
            float2 a = unpack2(acc[r][q]);
            float2 b = unpack2(b0p[q]);
            hA[r][q] = pack2(lrelu(a.x + b.x), lrelu(a.y + b.y));
        }
    #pragma unroll
    for (int r = 0; r < 4; r++)
        #pragma unroll
        for (int q = 0; q < 4; q++) {
            hB[r][q] = __shfl_xor_sync(0xffffffffu, hA[r][q], 8);
            a2[r][q] = b1p[q];
        }
    // accumulate a2 (my i'-half) over all 16 jj: 8 from hA (jj=ih*8+m), 8 from hB
    #pragma unroll
    for (int m = 0; m < 8; m++) {
        ull wa0, wa1, wa2, wa3, wb0, wb1, wb2, wb3;
        lds16(wa0, wa1, &S.w1s[ih * 8 + m][tt * 2 + ih][0]);
        lds16(wa2, wa3, &S.w1s[ih * 8 + m][tt * 2 + ih][4]);
        lds16(wb0, wb1, &S.w1s[(1 - ih) * 8 + m][tt * 2 + ih][0]);
        lds16(wb2, wb3, &S.w1s[(1 - ih) * 8 + m][tt * 2 + ih][4]);
        #pragma unroll
        for (int r = 0; r < 4; r++) {
            float2 ha = unpack2(hA[r][m >> 1]);
            ull hv = dup2((m & 1) ? ha.y : ha.x);
            ffma2(a2[r][0], wa0, hv); ffma2(a2[r][1], wa1, hv);
            ffma2(a2[r][2], wa2, hv); ffma2(a2[r][3], wa3, hv);
            float2 hb = unpack2(hB[r][m >> 1]);
            ull hv2 = dup2((m & 1) ? hb.y : hb.x);
            ffma2(a2[r][0], wb0, hv2); ffma2(a2[r][1], wb1, hv2);
            ffma2(a2[r][2], wb2, hv2); ffma2(a2[r][3], wb3, hv2);
        }
    }
    // layer 2: partial over my i'-half, combine via shfl
    #pragma unroll
    for (int r = 0; r < 4; r++) {
        ull o0p = 0ull, o1p = 0ull;
        #pragma unroll
        for (int q = 0; q < 4; q++) {
            float2 g = unpack2(a2[r][q]);
            ull gp = pack2(lrelu(g.x), lrelu(g.y));
            ffma2(o0p, w2p0[q], gp);
            ffma2(o1p, w2p1[q], gp);
        }
        float2 s0 = unpack2(o0p), s1 = unpack2(o1p);
        float o0 = s0.x + s0.y, o1 = s1.x + s1.y;
        o0 += __shfl_xor_sync(0xffffffffu, o0, 8);
        o1 += __shfl_xor_sync(0xffffffffu, o1, 8);
        if (ih == 0 && t < Dv) {
            int b = bbase + warp * 8 + bs * 4 + r;
            reinterpret_cast<float2*>(out)[b * Dv + t] =
                make_float2(o0 + b2v.x, o1 + b2v.y);
        }
    }
}

extern "C" void kernel_launch(void* const* d_in, const int* in_sizes, int n_in,
                              void* d_out, int out_size)
{
    const float* x   = (const float*)d_in[0];
    const float* la  = (const float*)d_in[1];
    const float* nz  = (const float*)d_in[2];
    const float* W0  = (const float*)d_in[3];
    const float* b0  = (const float*)d_in[4];
    const float* W1  = (const float*)d_in[5];
    const float* b1  = (const float*)d_in[6];
    const float* W2  = (const float*)d_in[7];
    const float* b2  = (const float*)d_in[8];
    float* out = (float*)d_out;

    cudaFuncSetAttribute(fused_nri_kernel,
                         cudaFuncAttributeMaxDynamicSharedMemorySize,
                         (int)sizeof(Smem));
    // 13 t-tiles x 64 b-blocks, 256 threads (8 warps x 8 rows)
    fused_nri_kernel<<<13 * 64, 256, sizeof(Smem)>>>(
        x, la, nz, W0, b0, W1, b1, W2, b2, out);
}